// round 14
// baseline (speedup 1.0000x reference)
#include <cuda_runtime.h>
#include <math.h>

#define TT 256
#define HH 512
#define SS (TT*HH)
#define TSQ (TT*TT)
#define EPSV 1e-5f
#define NCTA 296

// ---------------- scratch (device globals; no allocs allowed) ----------------
__device__ __align__(16) float g_part[48*SS];  // Zp/Bp[16SS] | Yp[16SS] | C1p[8SS] | C2p[8SS]
__device__ __align__(16) float g_Z [SS];
__device__ __align__(16) float g_Y [SS];
__device__ __align__(16) float g_D [SS];
__device__ __align__(16) float g_P [SS];
__device__ __align__(16) float g_BETA[TSQ];
__device__ __align__(16) float g_c [TT];
__device__ unsigned g_cnt = 0;
__device__ unsigned g_gen = 0;

// lower-triangle (incl diagonal) 64x64 block pairs of the 4x4 block grid
__device__ const int g_PR[10] = {0,1,1,2,2,2,3,3,3,3};
__device__ const int g_PC[10] = {0,0,1,0,1,2,0,1,2,3};

// ---------------- f32x2 packed FMA helpers ----------------
typedef unsigned long long u64;
__device__ __forceinline__ void ffma2(u64 &d, u64 a, u64 b) {
    asm("fma.rn.f32x2 %0, %1, %2, %3;" : "=l"(d) : "l"(a), "l"(b), "l"(d));
}
__device__ __forceinline__ u64 dup2(float x) {
    u64 r; asm("mov.b64 %0, {%1, %1};" : "=l"(r) : "f"(x)); return r;
}
__device__ __forceinline__ float2 unpk(u64 v) {
    float2 r; asm("mov.b64 {%0, %1}, %2;" : "=f"(r.x), "=f"(r.y) : "l"(v)); return r;
}

// ---------------- shared memory (reused by all phases; double-buffered) ----------------
struct __align__(16) Smem {
    float A[2][16][68];
    union {
        struct { float B1[2][16][68]; float B2[2][16][68]; } nb;  // 64-wide pair (Bp/corr)
        float Bw[2][16][132];                                      // 128-wide (Zp/Yp)
    } u;
    float red[3][16];
};

// ---------------- grid barrier: release/acquire ----------------
__device__ __forceinline__ void gbar() {
    __syncthreads();
    if (threadIdx.x == 0) {
        unsigned gen = g_gen;
        unsigned old;
        asm volatile("atom.add.release.gpu.u32 %0, [%1], 1;"
                     : "=r"(old) : "l"(&g_cnt) : "memory");
        if (old == NCTA - 1) {
            g_cnt = 0;
            asm volatile("st.release.gpu.u32 [%0], %1;"
                         :: "l"(&g_gen), "r"(gen + 1) : "memory");
        } else {
            unsigned cur;
            do {
                __nanosleep(32);
                asm volatile("ld.acquire.gpu.u32 %0, [%1];"
                             : "=r"(cur) : "l"(&g_gen) : "memory");
            } while (cur == gen);
        }
    }
    __syncthreads();
}

// ---------------- batched block reductions (256 threads) ----------------
template<int NV>
__device__ __forceinline__ void warpRedSumN(float* v) {
    #pragma unroll
    for (int o = 16; o > 0; o >>= 1) {
        #pragma unroll
        for (int n = 0; n < NV; ++n) v[n] += __shfl_xor_sync(0xffffffffu, v[n], o);
    }
}
template<int NV>
__device__ void blockRedSumN(float* v, float (*s)[16]) {
    warpRedSumN<NV>(v);
    int lane = threadIdx.x & 31, w = threadIdx.x >> 5;
    if (lane == 0) {
        #pragma unroll
        for (int n = 0; n < NV; ++n) s[n][w] = v[n];
    }
    __syncthreads();
    if (threadIdx.x < 32) {
        float x[NV];
        #pragma unroll
        for (int n = 0; n < NV; ++n) x[n] = (threadIdx.x < 8) ? s[n][threadIdx.x] : 0.f;
        warpRedSumN<NV>(x);
        if (threadIdx.x == 0) {
            #pragma unroll
            for (int n = 0; n < NV; ++n) s[n][8] = x[n];
        }
    }
    __syncthreads();
    #pragma unroll
    for (int n = 0; n < NV; ++n) v[n] = s[n][8];
    __syncthreads();
}

__device__ __forceinline__ float4 ld4(const float* p) {
    return __ldcg(reinterpret_cast<const float4*>(p));
}

// =================================================================
// 64x128 GEMM tile (4 rows x 8 cols per thread), f32x2 FMA.
// double-buffered, one __syncthreads per k-iter. A,B plain row-major.
// =================================================================
__device__ void gemm_wide(Smem* sm, const float* __restrict__ A,
                          const float* __restrict__ B, float* __restrict__ Cp,
                          int bm, int bn, int kbase, int zsl,
                          int Kc, int N, int Ktot, int cstride)
{
    const int tid = threadIdx.x;
    const int tx = tid & 15, ty = tid >> 4;
    const int ar = tid >> 2, ac4 = (tid & 3) << 2;   // A loader: 64 rows x 16 k
    const int brr = tid >> 4, bcc = (tid & 15) * 8;  // B loader: 16 k x 128 cols
    u64 acc[4][4] = {};
    const int niter = Kc >> 4;

    auto loadA = [&](int k0) -> float4 {
        return ld4(&A[(size_t)(bm + ar) * Ktot + kbase + k0 + ac4]);
    };
    auto loadB0 = [&](int k0) -> float4 {
        return ld4(&B[(size_t)(kbase + k0 + brr) * N + bn + bcc]);
    };
    auto loadB1 = [&](int k0) -> float4 {
        return ld4(&B[(size_t)(kbase + k0 + brr) * N + bn + bcc + 4]);
    };
    auto storeA = [&](int s, float4 v) {
        sm->A[s][ac4+0][ar] = v.x; sm->A[s][ac4+1][ar] = v.y;
        sm->A[s][ac4+2][ar] = v.z; sm->A[s][ac4+3][ar] = v.w;
    };
    auto storeB = [&](int s, float4 v0, float4 v1) {
        *reinterpret_cast<float4*>(&sm->u.Bw[s][brr][bcc])     = v0;
        *reinterpret_cast<float4*>(&sm->u.Bw[s][brr][bcc + 4]) = v1;
    };

    __syncthreads();   // protect smem reuse across tiles/phases
    float4 pa = loadA(0), pb0 = loadB0(0), pb1 = loadB1(0);
    storeA(0, pa); storeB(0, pb0, pb1);

    for (int it = 0; it < niter; ++it) {
        __syncthreads();
        if (it + 1 < niter) {
            int kn = (it + 1) << 4;
            pa = loadA(kn); pb0 = loadB0(kn); pb1 = loadB1(kn);
        }
        const int s = it & 1;
        #pragma unroll
        for (int k = 0; k < 16; ++k) {
            float4 av = *reinterpret_cast<const float4*>(&sm->A[s][k][ty*4]);
            const u64* bp = reinterpret_cast<const u64*>(&sm->u.Bw[s][k][tx*8]);
            u64 b0 = bp[0], b1 = bp[1], b2 = bp[2], b3 = bp[3];
            u64 a0 = dup2(av.x), a1 = dup2(av.y), a2 = dup2(av.z), a3 = dup2(av.w);
            ffma2(acc[0][0], a0, b0); ffma2(acc[0][1], a0, b1);
            ffma2(acc[0][2], a0, b2); ffma2(acc[0][3], a0, b3);
            ffma2(acc[1][0], a1, b0); ffma2(acc[1][1], a1, b1);
            ffma2(acc[1][2], a1, b2); ffma2(acc[1][3], a1, b3);
            ffma2(acc[2][0], a2, b0); ffma2(acc[2][1], a2, b1);
            ffma2(acc[2][2], a2, b2); ffma2(acc[2][3], a2, b3);
            ffma2(acc[3][0], a3, b0); ffma2(acc[3][1], a3, b1);
            ffma2(acc[3][2], a3, b2); ffma2(acc[3][3], a3, b3);
        }
        if (it + 1 < niter) { storeA((it+1) & 1, pa); storeB((it+1) & 1, pb0, pb1); }
    }
    float* C = Cp + (size_t)zsl * cstride;
    #pragma unroll
    for (int i = 0; i < 4; ++i) {
        int row = bm + ty*4 + i;
        float2 v0 = unpk(acc[i][0]), v1 = unpk(acc[i][1]);
        float2 v2 = unpk(acc[i][2]), v3 = unpk(acc[i][3]);
        size_t idx = (size_t)row * N + bn + tx*8;
        *reinterpret_cast<float4*>(&C[idx])     = make_float4(v0.x, v0.y, v1.x, v1.y);
        *reinterpret_cast<float4*>(&C[idx + 4]) = make_float4(v2.x, v2.y, v3.x, v3.y);
    }
}

// =================================================================
// 64x64 GEMM tile (Bp path): BTRANS, BFUSE (B = B .* Baux = h .* Z)
// =================================================================
__device__ void gemm_bp(Smem* sm, const float* __restrict__ A,
                        const float* __restrict__ B, const float* __restrict__ Baux,
                        float* __restrict__ Cp,
                        int bm, int bn, int kbase, int zsl,
                        int Kc, int N, int Ktot, int cstride)
{
    const int tid = threadIdx.x;
    const int tx = tid & 15, ty = tid >> 4;
    const int ar = tid >> 2, ac4 = (tid & 3) << 2;
    u64 acc[4][2] = {};
    const int niter = Kc >> 4;

    auto loadA = [&](int k0) -> float4 {
        return ld4(&A[(size_t)(bm + ar) * Ktot + kbase + k0 + ac4]);
    };
    auto loadB = [&](int k0) -> float4 {
        float4 v = ld4(&B[(size_t)(bn + ar) * Ktot + kbase + k0 + ac4]);
        float4 w = ld4(&Baux[(size_t)(bn + ar) * Ktot + kbase + k0 + ac4]);
        v.x *= w.x; v.y *= w.y; v.z *= w.z; v.w *= w.w;
        return v;
    };
    auto storeA = [&](int s, float4 v) {
        sm->A[s][ac4+0][ar] = v.x; sm->A[s][ac4+1][ar] = v.y;
        sm->A[s][ac4+2][ar] = v.z; sm->A[s][ac4+3][ar] = v.w;
    };
    auto storeB = [&](int s, float4 v) {
        sm->u.nb.B1[s][ac4+0][ar] = v.x; sm->u.nb.B1[s][ac4+1][ar] = v.y;
        sm->u.nb.B1[s][ac4+2][ar] = v.z; sm->u.nb.B1[s][ac4+3][ar] = v.w;
    };

    __syncthreads();
    float4 pa = loadA(0), pb = loadB(0);
    storeA(0, pa); storeB(0, pb);

    for (int it = 0; it < niter; ++it) {
        __syncthreads();
        if (it + 1 < niter) { pa = loadA((it+1) << 4); pb = loadB((it+1) << 4); }
        const int s = it & 1;
        #pragma unroll
        for (int k = 0; k < 16; ++k) {
            float4 av = *reinterpret_cast<const float4*>(&sm->A[s][k][ty*4]);
            const u64* bp = reinterpret_cast<const u64*>(&sm->u.nb.B1[s][k][tx*4]);
            u64 rb0 = bp[0], rb1 = bp[1];
            u64 a0 = dup2(av.x), a1 = dup2(av.y), a2 = dup2(av.z), a3 = dup2(av.w);
            ffma2(acc[0][0], a0, rb0); ffma2(acc[0][1], a0, rb1);
            ffma2(acc[1][0], a1, rb0); ffma2(acc[1][1], a1, rb1);
            ffma2(acc[2][0], a2, rb0); ffma2(acc[2][1], a2, rb1);
            ffma2(acc[3][0], a3, rb0); ffma2(acc[3][1], a3, rb1);
        }
        if (it + 1 < niter) { storeA((it+1) & 1, pa); storeB((it+1) & 1, pb); }
    }
    float* C = Cp + (size_t)zsl * cstride;
    #pragma unroll
    for (int i = 0; i < 4; ++i) {
        int row = bm + ty*4 + i;
        float2 v0 = unpk(acc[i][0]), v1 = unpk(acc[i][1]);
        *reinterpret_cast<float4*>(&C[(size_t)row * N + bn + tx*4]) =
            make_float4(v0.x, v0.y, v1.x, v1.y);
    }
}

// ---------------- Z = relu(sum 16 Zp + a) ----------------
__device__ void zred_tile(int tile, const float* Zp, const float* a, float* Z) {
    int i4 = tile * 1024 + threadIdx.x * 4;
    float4 r = make_float4(0.f, 0.f, 0.f, 0.f);
    #pragma unroll
    for (int s = 0; s < 16; ++s) {
        float4 v = ld4(&Zp[(size_t)s * SS + i4]);
        r.x += v.x; r.y += v.y; r.z += v.z; r.w += v.w;
    }
    float4 bb = ld4(&a[i4 & (HH - 1)]);
    r.x = fmaxf(r.x + bb.x, 0.f); r.y = fmaxf(r.y + bb.y, 0.f);
    r.z = fmaxf(r.z + bb.z, 0.f); r.w = fmaxf(r.w + bb.w, 0.f);
    *reinterpret_cast<float4*>(&Z[i4]) = r;
}

// ---------------- BETA = sum 16 Bp slices, lower-tri blocks only ----------------
__device__ void bsum_tile(int tile, const float* Bp, float* BETA) {
    const int blk = tile >> 2, sub = tile & 3;
    const int r = g_PR[blk] * 64 + sub * 16 + (threadIdx.x >> 4);
    const int c = g_PC[blk] * 64 + (threadIdx.x & 15) * 4;
    size_t off = (size_t)r * TT + c;
    float4 acc = make_float4(0.f, 0.f, 0.f, 0.f);
    #pragma unroll
    for (int s = 0; s < 16; ++s) {
        float4 v = ld4(&Bp[(size_t)s * TSQ + off]);
        acc.x += v.x; acc.y += v.y; acc.z += v.z; acc.w += v.w;
    }
    *reinterpret_cast<float4*>(&BETA[off]) = acc;
}

// ---------------- P = inclusive cumsum_t(h): 16 cols/tile, 16 thr/col ----------------
__device__ void prefix_tile(int p, const float* __restrict__ h, float* __restrict__ P) {
    const int q = p * 16 + (threadIdx.x >> 4);
    const int seg = threadIdx.x & 15;
    const int t0 = seg * 16;
    float v[16];
    #pragma unroll
    for (int i = 0; i < 16; ++i) v[i] = __ldcg(&h[(size_t)(t0 + i) * HH + q]);
    #pragma unroll
    for (int i = 1; i < 16; ++i) v[i] += v[i-1];
    float run = v[15];
    #pragma unroll
    for (int d = 1; d < 16; d <<= 1) {
        float n = __shfl_up_sync(0xffffffffu, run, d);
        if (seg >= d) run += n;
    }
    float off = run - v[15];
    #pragma unroll
    for (int i = 0; i < 16; ++i) P[(size_t)(t0 + i) * HH + q] = v[i] + off;
}

// ---------------- rows: Y reduce (16 slices), LN fwd, softmax grad, LN bwd ----------------
__device__ void rows_tile(Smem* sm, int t,
    const float* __restrict__ Yp, const float* __restrict__ h,
    const float* __restrict__ bvec, const float* __restrict__ gamma,
    const float* __restrict__ beta, const int* __restrict__ targets,
    float* __restrict__ Y, float* __restrict__ D, float* __restrict__ cvec)
{
    const int q0 = threadIdx.x, q1 = threadIdx.x + 256;
    const int tgt = targets[t];
    const size_t i0 = (size_t)t*HH + q0, i1 = (size_t)t*HH + q1;

    float u0 = bvec[q0], u1 = bvec[q1];
    #pragma unroll
    for (int s = 0; s < 16; ++s) {
        u0 += __ldcg(&Yp[(size_t)s*SS + i0]);
        u1 += __ldcg(&Yp[(size_t)s*SS + i1]);
    }
    float h0 = h[i0], h1 = h[i1];
    Y[i0] = u0; Y[i1] = u1;

    float r[3] = { u0 + u1, u0*u0 + u1*u1, h0 + h1 };
    blockRedSumN<3>(r, sm->red);
    float sum_h = r[2];
    float m = r[0] * (1.f / HH);
    float var = r[1] * (1.f / HH) - m * m;
    float rstd = rsqrtf(var + EPSV);
    float x0 = (u0 - m) * rstd, x1 = (u1 - m) * rstd;
    float g0 = gamma[q0], g1 = gamma[q1];
    float y0 = x0 * g0 + beta[q0];
    float y1 = x1 * g1 + beta[q1];

    float e0 = __expf(y0), e1 = __expf(y1);   // LN output: |y| bounded, no overflow
    float se[1] = { e0 + e1 };
    blockRedSumN<1>(se, sm->red);
    float inv_se = 1.f / se[0];
    float s0 = e0 * inv_se - (q0 == tgt ? 1.f : 0.f);
    float s1 = e1 * inv_se - (q1 == tgt ? 1.f : 0.f);
    float sg0 = s0 * g0, sg1 = s1 * g1;

    float r2[2] = { sg0 + sg1, sg0*x0 + sg1*x1 };
    blockRedSumN<2>(r2, sm->red);
    float msg  = r2[0] * (1.f / HH);
    float msgx = r2[1] * (1.f / HH);
    D[i0] = rstd * (sg0 - msg - x0 * msgx);
    D[i1] = rstd * (sg1 - msg - x1 * msgx);
    if (threadIdx.x == 0) cvec[t] = sum_h;
}

// ---------------- corr GEMM tile: A = tril_strict(BETA + c[i]), dual B ----------------
__device__ void corr_tile(Smem* sm, int tile,
    const float* __restrict__ BETA, const float* __restrict__ cvec,
    const float* __restrict__ D, const float* __restrict__ P,
    float* __restrict__ C1p, float* __restrict__ C2p)
{
    const int tid = threadIdx.x;
    const int bn = (tile & 7) * 64;
    const int bm = ((tile >> 3) & 3) * 64;
    const int z  = tile >> 5;
    const int tx = tid & 15, ty = tid >> 4;
    const int ar = tid >> 2, ac4 = (tid & 3) << 2;
    const int br = tid >> 4, bc4 = (tid & 15) << 2;
    float* O1 = C1p + (size_t)z * SS;
    float* O2 = C2p + (size_t)z * SS;

    const int k_lo = z * 32;
    if (k_lo >= bm + 64) return;   // dead tile: never read by ln for these rows

    auto loadA = [&](int k0) -> float4 {
        const int trow = bm + ar;
        float4 r = ld4(&BETA[(size_t)trow * TT + k0 + ac4]);
        float4 cc = ld4(&cvec[k0 + ac4]);
        r.x = (k0 + ac4 + 0 < trow) ? r.x + cc.x : 0.f;
        r.y = (k0 + ac4 + 1 < trow) ? r.y + cc.y : 0.f;
        r.z = (k0 + ac4 + 2 < trow) ? r.z + cc.z : 0.f;
        r.w = (k0 + ac4 + 3 < trow) ? r.w + cc.w : 0.f;
        return r;
    };
    auto storeA = [&](int s, float4 v) {
        sm->A[s][ac4+0][ar] = v.x; sm->A[s][ac4+1][ar] = v.y;
        sm->A[s][ac4+2][ar] = v.z; sm->A[s][ac4+3][ar] = v.w;
    };
    auto storeB = [&](int s, float4 d, float4 p) {
        *reinterpret_cast<float4*>(&sm->u.nb.B1[s][br][bc4]) = d;
        *reinterpret_cast<float4*>(&sm->u.nb.B2[s][br][bc4]) =
            make_float4(d.x*p.x, d.y*p.y, d.z*p.z, d.w*p.w);
    };

    __syncthreads();
    float4 pa = loadA(k_lo);
    float4 pd = ld4(&D[(size_t)(k_lo + br) * HH + bn + bc4]);
    float4 pp = ld4(&P[(size_t)(k_lo + br) * HH + bn + bc4]);
    storeA(0, pa); storeB(0, pd, pp);

    u64 acc1[4][2] = {}, acc2[4][2] = {};
    #pragma unroll
    for (int it = 0; it < 2; ++it) {
        __syncthreads();
        if (it == 0) {
            pa = loadA(k_lo + 16);
            pd = ld4(&D[(size_t)(k_lo + 16 + br) * HH + bn + bc4]);
            pp = ld4(&P[(size_t)(k_lo + 16 + br) * HH + bn + bc4]);
        }
        #pragma unroll
        for (int k = 0; k < 16; ++k) {
            float4 av = *reinterpret_cast<const float4*>(&sm->A[it][k][ty*4]);
            const u64* b1 = reinterpret_cast<const u64*>(&sm->u.nb.B1[it][k][tx*4]);
            const u64* b2 = reinterpret_cast<const u64*>(&sm->u.nb.B2[it][k][tx*4]);
            u64 r10 = b1[0], r11 = b1[1], r20 = b2[0], r21 = b2[1];
            u64 a0 = dup2(av.x), a1 = dup2(av.y), a2 = dup2(av.z), a3 = dup2(av.w);
            ffma2(acc1[0][0], a0, r10); ffma2(acc1[0][1], a0, r11);
            ffma2(acc2[0][0], a0, r20); ffma2(acc2[0][1], a0, r21);
            ffma2(acc1[1][0], a1, r10); ffma2(acc1[1][1], a1, r11);
            ffma2(acc2[1][0], a1, r20); ffma2(acc2[1][1], a1, r21);
            ffma2(acc1[2][0], a2, r10); ffma2(acc1[2][1], a2, r11);
            ffma2(acc2[2][0], a2, r20); ffma2(acc2[2][1], a2, r21);
            ffma2(acc1[3][0], a3, r10); ffma2(acc1[3][1], a3, r11);
            ffma2(acc2[3][0], a3, r20); ffma2(acc2[3][1], a3, r21);
        }
        if (it == 0) { storeA(1, pa); storeB(1, pd, pp); }
    }
    #pragma unroll
    for (int i = 0; i < 4; ++i) {
        size_t idx = (size_t)(bm + ty*4 + i) * HH + bn + tx*4;
        float2 u0 = unpk(acc1[i][0]), u1 = unpk(acc1[i][1]);
        float2 w0 = unpk(acc2[i][0]), w1 = unpk(acc2[i][1]);
        *reinterpret_cast<float4*>(&O1[idx]) = make_float4(u0.x, u0.y, u1.x, u1.y);
        *reinterpret_cast<float4*>(&O2[idx]) = make_float4(w0.x, w0.y, w1.x, w1.y);
    }
}

// ---------------- reduce live corr partials + PRE + final LN (1-pass var) ----------------
__device__ void ln_tile(Smem* sm, int t,
    const float* __restrict__ Y, const float* __restrict__ P,
    const float* __restrict__ C1p, const float* __restrict__ C2p,
    const float* __restrict__ gamma, const float* __restrict__ beta,
    float* __restrict__ out)
{
    const int q0 = threadIdx.x, q1 = threadIdx.x + 256;
    size_t i0 = (size_t)t*HH + q0, i1 = (size_t)t*HH + q1;

    const int smax = ((t >> 6) << 1) + 2;   // live split-K slices for this row block
    float c1a = 0.f, c1b = 0.f, c2a = 0.f, c2b = 0.f;
    for (int s = 0; s < smax; ++s) {
        c1a += __ldcg(&C1p[(size_t)s*SS + i0]);
        c1b += __ldcg(&C1p[(size_t)s*SS + i1]);
        c2a += __ldcg(&C2p[(size_t)s*SS + i0]);
        c2b += __ldcg(&C2p[(size_t)s*SS + i1]);
    }
    float u0 = __ldcg(&Y[i0]) - __ldcg(&P[i0]) * c1a + c2a;
    float u1 = __ldcg(&Y[i1]) - __ldcg(&P[i1]) * c1b + c2b;

    float r[2] = { u0 + u1, u0*u0 + u1*u1 };
    blockRedSumN<2>(r, sm->red);
    float m = r[0] * (1.f / HH);
    float var = r[1] * (1.f / HH) - m * m;
    float rstd = rsqrtf(var + EPSV);
    out[i0] = (u0 - m) * rstd * gamma[q0] + beta[q0];
    out[i1] = (u1 - m) * rstd * gamma[q1] + beta[q1];
}

// =================================================================
// mega kernel: 6 phases, 5 barriers, 296 persistent CTAs (2/SM)
// =================================================================
__global__ __launch_bounds__(256, 2) void mega_kernel(
    const float* __restrict__ h, const float* __restrict__ U,
    const float* __restrict__ W, const float* __restrict__ a,
    const float* __restrict__ b, const float* __restrict__ gamma,
    const float* __restrict__ beta, const int* __restrict__ tgts,
    float* __restrict__ out)
{
    __shared__ Smem sm;
    float* Zp  = g_part;                 // 16 slices SS (phase 1, wide, split-K 16)
    float* Yp  = g_part + 16*(size_t)SS; // 16 slices SS (phase 3, wide, split-K 16)
    float* Bp  = g_part;                 // 16 slices TSQ (phase 3; safe alias of Zp)
    float* C1p = g_part + 32*(size_t)SS; // 8 slices SS
    float* C2p = g_part + 40*(size_t)SS; // 8 slices SS

    // Phase 1: Zp = h @ U partials (64x128 tiles, split-K 16, 256 tiles) + P prefix (32)
    for (int tile = blockIdx.x; tile < 288; tile += gridDim.x) {
        if (tile < 256) {
            int bn = (tile & 3) * 128, bm = ((tile >> 2) & 3) * 64, z = tile >> 4;
            gemm_wide(&sm, h, U, Zp, bm, bn, z*32, z, 32, HH, HH, SS);
        } else prefix_tile(tile - 256, h, g_P);
    }
    gbar();
    // Phase 2: Z = relu(sum 16 Zp + a)  (128 tiles)
    for (int tile = blockIdx.x; tile < 128; tile += gridDim.x)
        zred_tile(tile, Zp, a, g_Z);
    gbar();
    // Phase 3: Yp = Z @ W (64x128 tiles, split-K 16, tiles 0-255)
    //        + Bp = Z @ (h.*Z)^T lower-tri (split-K 16, tiles 256-415)
    for (int tile = blockIdx.x; tile < 416; tile += gridDim.x) {
        if (tile < 256) {
            int bn = (tile & 3) * 128, bm = ((tile >> 2) & 3) * 64, z = tile >> 4;
            gemm_wide(&sm, g_Z, W, Yp, bm, bn, z*32, z, 32, HH, HH, SS);
        } else {
            int tt = tile - 256;
            int blk = tt % 10, z = tt / 10;
            gemm_bp(&sm, g_Z, h, g_Z, Bp, g_PR[blk]*64, g_PC[blk]*64, z*32, z, 32, TT, HH, TSQ);
        }
    }
    gbar();
    // Phase 4: rows -> Y, D, c (tiles 0-255) + BETA = sum Bp lower-tri (tiles 256-295)
    for (int tile = blockIdx.x; tile < 296; tile += gridDim.x) {
        if (tile < 256) rows_tile(&sm, tile, Yp, h, b, gamma, beta, tgts, g_Y, g_D, g_c);
        else            bsum_tile(tile - 256, Bp, g_BETA);
    }
    gbar();
    // Phase 5: C1p/C2p = tril_strict(BETA + c) @ {D, P*D} partials (split-K 8; dead skipped)
    for (int tile = blockIdx.x; tile < 256; tile += gridDim.x)
        corr_tile(&sm, tile, g_BETA, g_c, g_D, g_P, C1p, C2p);
    gbar();
    // Phase 6: out = LN(Y - P*C1 + C2)
    for (int t = blockIdx.x; t < TT; t += gridDim.x)
        ln_tile(&sm, t, g_Y, g_P, C1p, C2p, gamma, beta, out);
}

// ---------------- launch ----------------
extern "C" void kernel_launch(void* const* d_in, const int* in_sizes, int n_in,
                              void* d_out, int out_size)
{
    const float* h     = (const float*)d_in[0];
    const float* U     = (const float*)d_in[1];
    const float* W     = (const float*)d_in[2];
    const float* a     = (const float*)d_in[3];
    const float* b     = (const float*)d_in[4];
    const float* gamma = (const float*)d_in[5];
    const float* beta  = (const float*)d_in[6];
    const int*   tgts  = (const int*)d_in[7];
    float* out = (float*)d_out;

    mega_kernel<<<NCTA, 256>>>(h, U, W, a, b, gamma, beta, tgts, out);
}

// round 16
// speedup vs baseline: 1.7621x; 1.7621x over previous
#include <cuda_runtime.h>
#include <math.h>

#define TT 256
#define HH 512
#define SS (TT*HH)
#define TSQ (TT*TT)
#define EPSV 1e-5f
#define NCTA 296

// ---------------- scratch (device globals; no allocs allowed) ----------------
__device__ __align__(16) float g_part[32*SS];  // Zp/Bp | Yp | C1p | C2p
__device__ __align__(16) float g_Z [SS];
__device__ __align__(16) float g_Y [SS];
__device__ __align__(16) float g_D [SS];
__device__ __align__(16) float g_P [SS];
__device__ __align__(16) float g_BETA[TSQ];
__device__ __align__(16) float g_c [TT];
__device__ unsigned g_cnt = 0;
__device__ unsigned g_gen = 0;

// lower-triangle (incl diagonal) 64x64 block pairs of the 4x4 block grid
__device__ const int g_PR[10] = {0,1,1,2,2,2,3,3,3,3};
__device__ const int g_PC[10] = {0,0,1,0,1,2,0,1,2,3};

// ---------------- f32x2 packed FMA helpers ----------------
typedef unsigned long long u64;
__device__ __forceinline__ void ffma2(u64 &d, u64 a, u64 b) {
    asm("fma.rn.f32x2 %0, %1, %2, %3;" : "=l"(d) : "l"(a), "l"(b), "l"(d));
}
__device__ __forceinline__ u64 dup2(float x) {
    u64 r; asm("mov.b64 %0, {%1, %1};" : "=l"(r) : "f"(x)); return r;
}
__device__ __forceinline__ float2 unpk(u64 v) {
    float2 r; asm("mov.b64 {%0, %1}, %2;" : "=f"(r.x), "=f"(r.y) : "l"(v)); return r;
}

// ---------------- shared memory (reused by all phases; double-buffered) ----------------
struct __align__(16) Smem {
    float A [2][16][68];
    float B1[2][16][68];
    float B2[2][16][68];   // corr only
    float red[3][16];
    float tg[2];           // broadcast of (x_tgt, g_tgt) in rows phase
};

// ---------------- grid barrier: release/acquire ----------------
__device__ __forceinline__ void gbar() {
    __syncthreads();
    if (threadIdx.x == 0) {
        unsigned gen = g_gen;
        unsigned old;
        asm volatile("atom.add.release.gpu.u32 %0, [%1], 1;"
                     : "=r"(old) : "l"(&g_cnt) : "memory");
        if (old == NCTA - 1) {
            g_cnt = 0;
            asm volatile("st.release.gpu.u32 [%0], %1;"
                         :: "l"(&g_gen), "r"(gen + 1) : "memory");
        } else {
            unsigned cur;
            do {
                __nanosleep(32);
                asm volatile("ld.acquire.gpu.u32 %0, [%1];"
                             : "=r"(cur) : "l"(&g_gen) : "memory");
            } while (cur == gen);
        }
    }
    __syncthreads();
}

// ---------------- batched block reductions (256 threads) ----------------
template<int NV>
__device__ __forceinline__ void warpRedSumN(float* v) {
    #pragma unroll
    for (int o = 16; o > 0; o >>= 1) {
        #pragma unroll
        for (int n = 0; n < NV; ++n) v[n] += __shfl_xor_sync(0xffffffffu, v[n], o);
    }
}
template<int NV>
__device__ void blockRedSumN(float* v, float (*s)[16]) {
    warpRedSumN<NV>(v);
    int lane = threadIdx.x & 31, w = threadIdx.x >> 5;
    if (lane == 0) {
        #pragma unroll
        for (int n = 0; n < NV; ++n) s[n][w] = v[n];
    }
    __syncthreads();
    if (threadIdx.x < 32) {
        float x[NV];
        #pragma unroll
        for (int n = 0; n < NV; ++n) x[n] = (threadIdx.x < 8) ? s[n][threadIdx.x] : 0.f;
        warpRedSumN<NV>(x);
        if (threadIdx.x == 0) {
            #pragma unroll
            for (int n = 0; n < NV; ++n) s[n][8] = x[n];
        }
    }
    __syncthreads();
    #pragma unroll
    for (int n = 0; n < NV; ++n) v[n] = s[n][8];
    __syncthreads();
}

__device__ __forceinline__ float4 ld4(const float* p) {
    return __ldcg(reinterpret_cast<const float4*>(p));
}

// =================================================================
// 64x64 GEMM tile, f32x2 FMA, float A smem + in-loop dup,
// double-buffered (one __syncthreads per k-iter). Explicit coords.
// BFUSE (with BTRANS): B element = B[..]*Baux[..]  (builds h .* Z)
// =================================================================
template<bool BTRANS, bool BFUSE>
__device__ void gemm_tile(Smem* sm, const float* __restrict__ A,
                          const float* __restrict__ B, const float* __restrict__ Baux,
                          float* __restrict__ Cp,
                          int bm, int bn, int kbase, int zsl,
                          int Kc, int N, int Ktot, int cstride)
{
    const int tid = threadIdx.x;
    const int tx = tid & 15, ty = tid >> 4;
    const int ar = tid >> 2, ac4 = (tid & 3) << 2;
    const int br = tid >> 4, bc4 = (tid & 15) << 2;
    u64 acc[4][2] = {};
    const int niter = Kc >> 4;

    auto loadA = [&](int k0) -> float4 {
        return ld4(&A[(size_t)(bm + ar) * Ktot + kbase + k0 + ac4]);
    };
    auto loadB = [&](int k0) -> float4 {
        if (!BTRANS) return ld4(&B[(size_t)(kbase + k0 + br) * N + bn + bc4]);
        else {
            float4 v = ld4(&B[(size_t)(bn + ar) * Ktot + kbase + k0 + ac4]);
            if (BFUSE) {
                float4 w = ld4(&Baux[(size_t)(bn + ar) * Ktot + kbase + k0 + ac4]);
                v.x *= w.x; v.y *= w.y; v.z *= w.z; v.w *= w.w;
            }
            return v;
        }
    };
    auto storeA = [&](int s, float4 v) {
        sm->A[s][ac4+0][ar] = v.x; sm->A[s][ac4+1][ar] = v.y;
        sm->A[s][ac4+2][ar] = v.z; sm->A[s][ac4+3][ar] = v.w;
    };
    auto storeB = [&](int s, float4 v) {
        if (!BTRANS) {
            *reinterpret_cast<float4*>(&sm->B1[s][br][bc4]) = v;
        } else {
            sm->B1[s][ac4+0][ar] = v.x; sm->B1[s][ac4+1][ar] = v.y;
            sm->B1[s][ac4+2][ar] = v.z; sm->B1[s][ac4+3][ar] = v.w;
        }
    };

    __syncthreads();   // protect smem reuse across tiles/phases
    float4 pa = loadA(0), pb = loadB(0);
    storeA(0, pa); storeB(0, pb);

    for (int it = 0; it < niter; ++it) {
        __syncthreads();
        if (it + 1 < niter) { pa = loadA((it+1) << 4); pb = loadB((it+1) << 4); }
        const int s = it & 1;
        #pragma unroll
        for (int k = 0; k < 16; ++k) {
            float4 av = *reinterpret_cast<const float4*>(&sm->A[s][k][ty*4]);
            const u64* bp = reinterpret_cast<const u64*>(&sm->B1[s][k][tx*4]);
            u64 rb0 = bp[0], rb1 = bp[1];
            u64 a0 = dup2(av.x), a1 = dup2(av.y), a2 = dup2(av.z), a3 = dup2(av.w);
            ffma2(acc[0][0], a0, rb0); ffma2(acc[0][1], a0, rb1);
            ffma2(acc[1][0], a1, rb0); ffma2(acc[1][1], a1, rb1);
            ffma2(acc[2][0], a2, rb0); ffma2(acc[2][1], a2, rb1);
            ffma2(acc[3][0], a3, rb0); ffma2(acc[3][1], a3, rb1);
        }
        if (it + 1 < niter) { storeA((it+1) & 1, pa); storeB((it+1) & 1, pb); }
    }
    float* C = Cp + (size_t)zsl * cstride;
    #pragma unroll
    for (int i = 0; i < 4; ++i) {
        int row = bm + ty*4 + i;
        float2 v0 = unpk(acc[i][0]), v1 = unpk(acc[i][1]);
        *reinterpret_cast<float4*>(&C[(size_t)row * N + bn + tx*4]) =
            make_float4(v0.x, v0.y, v1.x, v1.y);
    }
}

// ---------------- Z = relu(sum 8 Zp + a) ----------------
__device__ void zred_tile(int tile, const float* Zp, const float* a, float* Z) {
    int i4 = tile * 1024 + threadIdx.x * 4;
    float4 r = make_float4(0.f, 0.f, 0.f, 0.f);
    #pragma unroll
    for (int s = 0; s < 8; ++s) {
        float4 v = ld4(&Zp[(size_t)s * SS + i4]);
        r.x += v.x; r.y += v.y; r.z += v.z; r.w += v.w;
    }
    float4 bb = ld4(&a[i4 & (HH - 1)]);
    r.x = fmaxf(r.x + bb.x, 0.f); r.y = fmaxf(r.y + bb.y, 0.f);
    r.z = fmaxf(r.z + bb.z, 0.f); r.w = fmaxf(r.w + bb.w, 0.f);
    *reinterpret_cast<float4*>(&Z[i4]) = r;
}

// ---------------- BETA = sum 16 Bp slices, lower-tri blocks only ----------------
// 40 tiles: tile -> block pairs[tile/4], 16-row stripe (tile%4)
__device__ void bsum_tile(int tile, const float* Bp, float* BETA) {
    const int blk = tile >> 2, sub = tile & 3;
    const int r = g_PR[blk] * 64 + sub * 16 + (threadIdx.x >> 4);
    const int c = g_PC[blk] * 64 + (threadIdx.x & 15) * 4;
    size_t off = (size_t)r * TT + c;
    float4 acc = make_float4(0.f, 0.f, 0.f, 0.f);
    #pragma unroll
    for (int s = 0; s < 16; ++s) {
        float4 v = ld4(&Bp[(size_t)s * TSQ + off]);
        acc.x += v.x; acc.y += v.y; acc.z += v.z; acc.w += v.w;
    }
    *reinterpret_cast<float4*>(&BETA[off]) = acc;
}

// ---------------- P = inclusive cumsum_t(h): 16 cols/tile, 16 thr/col ----------------
__device__ void prefix_tile(int p, const float* __restrict__ h, float* __restrict__ P) {
    const int q = p * 16 + (threadIdx.x >> 4);
    const int seg = threadIdx.x & 15;
    const int t0 = seg * 16;
    float v[16];
    #pragma unroll
    for (int i = 0; i < 16; ++i) v[i] = __ldcg(&h[(size_t)(t0 + i) * HH + q]);
    #pragma unroll
    for (int i = 1; i < 16; ++i) v[i] += v[i-1];
    float run = v[15];
    #pragma unroll
    for (int d = 1; d < 16; d <<= 1) {
        float n = __shfl_up_sync(0xffffffffu, run, d);
        if (seg >= d) run += n;
    }
    float off = run - v[15];
    #pragma unroll
    for (int i = 0; i < 16; ++i) P[(size_t)(t0 + i) * HH + q] = v[i] + off;
}

// ---------------- rows: Y reduce, LN fwd (1-pass var), softmax+LN bwd (merged) ----------------
// Merged backward reductions:
//   sum(sg)   = inv_se * sum(e*g)   - g_tgt
//   sum(sg*x) = inv_se * sum(e*g*x) - g_tgt * x_tgt
// -> one 3-batch reduction {e, e*g, e*g*x}; target terms broadcast via smem.
__device__ void rows_tile(Smem* sm, int t,
    const float* __restrict__ Yp, const float* __restrict__ h,
    const float* __restrict__ bvec, const float* __restrict__ gamma,
    const float* __restrict__ beta, const int* __restrict__ targets,
    float* __restrict__ Y, float* __restrict__ D, float* __restrict__ cvec)
{
    const int q0 = threadIdx.x, q1 = threadIdx.x + 256;
    const int tgt = targets[t];
    const size_t i0 = (size_t)t*HH + q0, i1 = (size_t)t*HH + q1;

    float u0 = bvec[q0], u1 = bvec[q1];
    #pragma unroll
    for (int s = 0; s < 8; ++s) {
        u0 += __ldcg(&Yp[(size_t)s*SS + i0]);
        u1 += __ldcg(&Yp[(size_t)s*SS + i1]);
    }
    float h0 = h[i0], h1 = h[i1];
    Y[i0] = u0; Y[i1] = u1;

    float r[3] = { u0 + u1, u0*u0 + u1*u1, h0 + h1 };
    blockRedSumN<3>(r, sm->red);
    float sum_h = r[2];
    float m = r[0] * (1.f / HH);
    float var = r[1] * (1.f / HH) - m * m;
    float rstd = rsqrtf(var + EPSV);
    float x0 = (u0 - m) * rstd, x1 = (u1 - m) * rstd;
    float g0 = gamma[q0], g1 = gamma[q1];
    float y0 = x0 * g0 + beta[q0];
    float y1 = x1 * g1 + beta[q1];

    // broadcast target-element (x, g); the reduction's syncs order it
    if (q0 == tgt) { sm->tg[0] = x0; sm->tg[1] = g0; }
    if (q1 == tgt) { sm->tg[0] = x1; sm->tg[1] = g1; }

    float e0 = __expf(y0), e1 = __expf(y1);   // LN output: |y| bounded, no overflow
    float eg0 = e0 * g0, eg1 = e1 * g1;
    float r2[3] = { e0 + e1, eg0 + eg1, eg0*x0 + eg1*x1 };
    blockRedSumN<3>(r2, sm->red);
    float inv_se = 1.f / r2[0];
    float xt = sm->tg[0], gt = sm->tg[1];
    float msg  = (inv_se * r2[1] - gt)      * (1.f / HH);
    float msgx = (inv_se * r2[2] - gt * xt) * (1.f / HH);

    float sg0 = eg0 * inv_se - (q0 == tgt ? g0 : 0.f);
    float sg1 = eg1 * inv_se - (q1 == tgt ? g1 : 0.f);
    D[i0] = rstd * (sg0 - msg - x0 * msgx);
    D[i1] = rstd * (sg1 - msg - x1 * msgx);
    if (threadIdx.x == 0) cvec[t] = sum_h;
}

// ---------------- corr GEMM tile: A = tril_strict(BETA + c[i]), dual B ----------------
// split-K 8, Kc=32. Dead tiles (k_lo >= bm+64) skipped entirely;
// ln reads only live slices (s < 2*(t/64)+2).
__device__ void corr_tile(Smem* sm, int tile,
    const float* __restrict__ BETA, const float* __restrict__ cvec,
    const float* __restrict__ D, const float* __restrict__ P,
    float* __restrict__ C1p, float* __restrict__ C2p)
{
    const int tid = threadIdx.x;
    const int bn = (tile & 7) * 64;
    const int bm = ((tile >> 3) & 3) * 64;
    const int z  = tile >> 5;
    const int tx = tid & 15, ty = tid >> 4;
    const int ar = tid >> 2, ac4 = (tid & 3) << 2;
    const int br = tid >> 4, bc4 = (tid & 15) << 2;
    float* O1 = C1p + (size_t)z * SS;
    float* O2 = C2p + (size_t)z * SS;

    const int k_lo = z * 32;
    if (k_lo >= bm + 64) return;   // dead tile: never read by ln for these rows

    auto loadA = [&](int k0) -> float4 {
        const int trow = bm + ar;
        float4 r = ld4(&BETA[(size_t)trow * TT + k0 + ac4]);
        float4 cc = ld4(&cvec[k0 + ac4]);
        r.x = (k0 + ac4 + 0 < trow) ? r.x + cc.x : 0.f;
        r.y = (k0 + ac4 + 1 < trow) ? r.y + cc.y : 0.f;
        r.z = (k0 + ac4 + 2 < trow) ? r.z + cc.z : 0.f;
        r.w = (k0 + ac4 + 3 < trow) ? r.w + cc.w : 0.f;
        return r;
    };
    auto storeA = [&](int s, float4 v) {
        sm->A[s][ac4+0][ar] = v.x; sm->A[s][ac4+1][ar] = v.y;
        sm->A[s][ac4+2][ar] = v.z; sm->A[s][ac4+3][ar] = v.w;
    };
    auto storeB = [&](int s, float4 d, float4 p) {
        *reinterpret_cast<float4*>(&sm->B1[s][br][bc4]) = d;
        *reinterpret_cast<float4*>(&sm->B2[s][br][bc4]) =
            make_float4(d.x*p.x, d.y*p.y, d.z*p.z, d.w*p.w);
    };

    __syncthreads();
    float4 pa = loadA(k_lo);
    float4 pd = ld4(&D[(size_t)(k_lo + br) * HH + bn + bc4]);
    float4 pp = ld4(&P[(size_t)(k_lo + br) * HH + bn + bc4]);
    storeA(0, pa); storeB(0, pd, pp);

    u64 acc1[4][2] = {}, acc2[4][2] = {};
    #pragma unroll
    for (int it = 0; it < 2; ++it) {
        __syncthreads();
        if (it == 0) {
            pa = loadA(k_lo + 16);
            pd = ld4(&D[(size_t)(k_lo + 16 + br) * HH + bn + bc4]);
            pp = ld4(&P[(size_t)(k_lo + 16 + br) * HH + bn + bc4]);
        }
        #pragma unroll
        for (int k = 0; k < 16; ++k) {
            float4 av = *reinterpret_cast<const float4*>(&sm->A[it][k][ty*4]);
            const u64* b1 = reinterpret_cast<const u64*>(&sm->B1[it][k][tx*4]);
            const u64* b2 = reinterpret_cast<const u64*>(&sm->B2[it][k][tx*4]);
            u64 r10 = b1[0], r11 = b1[1], r20 = b2[0], r21 = b2[1];
            u64 a0 = dup2(av.x), a1 = dup2(av.y), a2 = dup2(av.z), a3 = dup2(av.w);
            ffma2(acc1[0][0], a0, r10); ffma2(acc1[0][1], a0, r11);
            ffma2(acc2[0][0], a0, r20); ffma2(acc2[0][1], a0, r21);
            ffma2(acc1[1][0], a1, r10); ffma2(acc1[1][1], a1, r11);
            ffma2(acc2[1][0], a1, r20); ffma2(acc2[1][1], a1, r21);
            ffma2(acc1[2][0], a2, r10); ffma2(acc1[2][1], a2, r11);
            ffma2(acc2[2][0], a2, r20); ffma2(acc2[2][1], a2, r21);
            ffma2(acc1[3][0], a3, r10); ffma2(acc1[3][1], a3, r11);
            ffma2(acc2[3][0], a3, r20); ffma2(acc2[3][1], a3, r21);
        }
        if (it == 0) { storeA(1, pa); storeB(1, pd, pp); }
    }
    #pragma unroll
    for (int i = 0; i < 4; ++i) {
        size_t idx = (size_t)(bm + ty*4 + i) * HH + bn + tx*4;
        float2 u0 = unpk(acc1[i][0]), u1 = unpk(acc1[i][1]);
        float2 w0 = unpk(acc2[i][0]), w1 = unpk(acc2[i][1]);
        *reinterpret_cast<float4*>(&O1[idx]) = make_float4(u0.x, u0.y, u1.x, u1.y);
        *reinterpret_cast<float4*>(&O2[idx]) = make_float4(w0.x, w0.y, w1.x, w1.y);
    }
}

// ---------------- reduce live corr partials + PRE + final LN (1-pass var) ----------------
__device__ void ln_tile(Smem* sm, int t,
    const float* __restrict__ Y, const float* __restrict__ P,
    const float* __restrict__ C1p, const float* __restrict__ C2p,
    const float* __restrict__ gamma, const float* __restrict__ beta,
    float* __restrict__ out)
{
    const int q0 = threadIdx.x, q1 = threadIdx.x + 256;
    size_t i0 = (size_t)t*HH + q0, i1 = (size_t)t*HH + q1;

    const int smax = ((t >> 6) << 1) + 2;   // live split-K slices for this row block
    float c1a = 0.f, c1b = 0.f, c2a = 0.f, c2b = 0.f;
    for (int s = 0; s < smax; ++s) {
        c1a += __ldcg(&C1p[(size_t)s*SS + i0]);
        c1b += __ldcg(&C1p[(size_t)s*SS + i1]);
        c2a += __ldcg(&C2p[(size_t)s*SS + i0]);
        c2b += __ldcg(&C2p[(size_t)s*SS + i1]);
    }
    float u0 = __ldcg(&Y[i0]) - __ldcg(&P[i0]) * c1a + c2a;
    float u1 = __ldcg(&Y[i1]) - __ldcg(&P[i1]) * c1b + c2b;

    float r[2] = { u0 + u1, u0*u0 + u1*u1 };
    blockRedSumN<2>(r, sm->red);
    float m = r[0] * (1.f / HH);
    float var = r[1] * (1.f / HH) - m * m;
    float rstd = rsqrtf(var + EPSV);
    out[i0] = (u0 - m) * rstd * gamma[q0] + beta[q0];
    out[i1] = (u1 - m) * rstd * gamma[q1] + beta[q1];
}

// =================================================================
// mega kernel: 6 phases, 5 barriers, 296 persistent CTAs, static scheduling
// =================================================================
__global__ __launch_bounds__(256, 3) void mega_kernel(
    const float* __restrict__ h, const float* __restrict__ U,
    const float* __restrict__ W, const float* __restrict__ a,
    const float* __restrict__ b, const float* __restrict__ gamma,
    const float* __restrict__ beta, const int* __restrict__ tgts,
    float* __restrict__ out)
{
    __shared__ Smem sm;
    float* Zp  = g_part;                 // 8 slices SS (phase 1)
    float* Yp  = g_part + 8*(size_t)SS;  // 8 slices SS (phase 3)
    float* Bp  = g_part;                 // 16 slices TSQ (phase 3; safe alias of Zp)
    float* C1p = g_part + 16*(size_t)SS; // 8 slices SS
    float* C2p = g_part + 24*(size_t)SS; // 8 slices SS

    // Phase 1: Zp = h @ U partials (split-K 8, 256 tiles) + P prefix (32 tiles)
    for (int tile = blockIdx.x; tile < 288; tile += gridDim.x) {
        if (tile < 256) {
            int bn = (tile & 7) * 64, bm = ((tile >> 3) & 3) * 64, z = tile >> 5;
            gemm_tile<false,false>(&sm, h, U, nullptr, Zp, bm, bn, z*64, z, 64, HH, HH, SS);
        } else prefix_tile(tile - 256, h, g_P);
    }
    gbar();
    // Phase 2: Z = relu(sum Zp + a)  (128 tiles)
    for (int tile = blockIdx.x; tile < 128; tile += gridDim.x)
        zred_tile(tile, Zp, a, g_Z);
    gbar();
    // Phase 3: Yp = Z @ W (split-K 8, tiles 0-255)
    //        + Bp = Z @ (h.*Z)^T, lower-tri blocks only (split-K 16, tiles 256-415)
    for (int tile = blockIdx.x; tile < 416; tile += gridDim.x) {
        if (tile < 256) {
            int bn = (tile & 7) * 64, bm = ((tile >> 3) & 3) * 64, z = tile >> 5;
            gemm_tile<false,false>(&sm, g_Z, W, nullptr, Yp, bm, bn, z*64, z, 64, HH, HH, SS);
        } else {
            int tt = tile - 256;
            int blk = tt % 10, z = tt / 10;
            int bm = g_PR[blk] * 64, bn = g_PC[blk] * 64;
            gemm_tile<true, true >(&sm, g_Z, h, g_Z, Bp, bm, bn, z*32, z, 32, TT, HH, TSQ);
        }
    }
    gbar();
    // Phase 4: rows -> Y, D, c (tiles 0-255) + BETA = sum Bp lower-tri (tiles 256-295)
    for (int tile = blockIdx.x; tile < 296; tile += gridDim.x) {
        if (tile < 256) rows_tile(&sm, tile, Yp, h, b, gamma, beta, tgts, g_Y, g_D, g_c);
        else            bsum_tile(tile - 256, Bp, g_BETA);
    }
    gbar();
    // Phase 5: C1p/C2p = tril_strict(BETA + c) @ {D, P*D} partials (split-K 8; dead skipped)
    for (int tile = blockIdx.x; tile < 256; tile += gridDim.x)
        corr_tile(&sm, tile, g_BETA, g_c, g_D, g_P, C1p, C2p);
    gbar();
    // Phase 6: out = LN(Y - P*C1 + C2)
    for (int t = blockIdx.x; t < TT; t += gridDim.x)
        ln_tile(&sm, t, g_Y, g_P, C1p, C2p, gamma, beta, out);
}

// ---------------- launch ----------------
extern "C" void kernel_launch(void* const* d_in, const int* in_sizes, int n_in,
                              void* d_out, int out_size)
{
    const float* h     = (const float*)d_in[0];
    const float* U     = (const float*)d_in[1];
    const float* W     = (const float*)d_in[2];
    const float* a     = (const float*)d_in[3];
    const float* b     = (const float*)d_in[4];
    const float* gamma = (const float*)d_in[5];
    const float* beta  = (const float*)d_in[6];
    const int*   tgts  = (const int*)d_in[7];
    float* out = (float*)d_out;

    mega_kernel<<<NCTA, 256>>>(h, U, W, a, b, gamma, beta, tgts, out);
}